// round 1
// baseline (speedup 1.0000x reference)
#include <cuda_runtime.h>

// Problem constants (SUBDIVISIONS=7, BATCH=16)
#define BATCH 16
#define YDIM  640
#define XDIM  256
#define BH    128            // YDIM/5
#define YX    (YDIM*XDIM)    // 163840
#define NV    (YX + 2)       // 163842 vertices
#define NV3   (NV*3)

// Scratch: per-batch interleaved xyz vertex positions and accumulated normals.
// ~31.5 MB each. Static __device__ arrays (no allocation allowed).
__device__ float  g_v [BATCH * NV3];
__device__ float  g_vn[BATCH * NV3];
__device__ double g_acc[3];   // [0]=pos, [1]=nor, [2]=lap

// ---------------------------------------------------------------------------
// K0: zero the normal accumulator and the loss accumulators
// ---------------------------------------------------------------------------
__global__ void k_zero() {
    long long idx = (long long)blockIdx.x * blockDim.x + threadIdx.x;
    if (idx < (long long)BATCH * NV3) g_vn[idx] = 0.0f;
    if (idx < 3) g_acc[idx] = 0.0;
}

// ---------------------------------------------------------------------------
// K1: build v = [grid verts ; top pole ; bottom pole], interleaved xyz
// inputs layout: (B, 3, Y, X) row-major
// ---------------------------------------------------------------------------
__global__ void k_build_v(const float* __restrict__ inp) {
    int vtx = blockIdx.x * blockDim.x + threadIdx.x;
    int b   = blockIdx.y;
    if (vtx > YX + 1) return;
    const float* base = inp + (size_t)b * 3 * YX;
    float* out = g_v + ((size_t)b * NV + vtx) * 3;
    if (vtx < YX) {
        out[0] = base[vtx];
        out[1] = base[YX + vtx];
        out[2] = base[2 * YX + vtx];
    } else if (vtx == YX) {
        // top pole: mean of rows {0,128,256,384,512}, col 0
        #pragma unroll
        for (int c = 0; c < 3; c++) {
            float s = 0.0f;
            #pragma unroll
            for (int i = 0; i < 5; i++) s += base[c * YX + (i * BH) * XDIM];
            out[c] = s * 0.2f;
        }
    } else {
        // bottom pole: mean of rows {127,255,383,511,639}, col X-1
        #pragma unroll
        for (int c = 0; c < 3; c++) {
            float s = 0.0f;
            #pragma unroll
            for (int i = 1; i <= 5; i++)
                s += base[c * YX + (i * BH - 1) * XDIM + (XDIM - 1)];
            out[c] = s * 0.2f;
        }
    }
}

// ---------------------------------------------------------------------------
// K2: face normals, atomic scatter-add into g_vn.  grid.y = batch.
// ---------------------------------------------------------------------------
__global__ void k_faces(const int* __restrict__ faces, int F) {
    int f = blockIdx.x * blockDim.x + threadIdx.x;
    int b = blockIdx.y;
    if (f >= F) return;
    int i0 = faces[3 * f], i1 = faces[3 * f + 1], i2 = faces[3 * f + 2];
    const float* vb = g_v  + (size_t)b * NV3;
    float*       nb = g_vn + (size_t)b * NV3;

    float x0 = vb[3 * i0], y0 = vb[3 * i0 + 1], z0 = vb[3 * i0 + 2];
    float x1 = vb[3 * i1], y1 = vb[3 * i1 + 1], z1 = vb[3 * i1 + 2];
    float x2 = vb[3 * i2], y2 = vb[3 * i2 + 1], z2 = vb[3 * i2 + 2];

    float e1x = x1 - x0, e1y = y1 - y0, e1z = z1 - z0;
    float e2x = x2 - x0, e2y = y2 - y0, e2z = z2 - z0;
    float nx = e1y * e2z - e1z * e2y;
    float ny = e1z * e2x - e1x * e2z;
    float nz = e1x * e2y - e1y * e2x;

    atomicAdd(nb + 3 * i0,     nx); atomicAdd(nb + 3 * i0 + 1, ny); atomicAdd(nb + 3 * i0 + 2, nz);
    atomicAdd(nb + 3 * i1,     nx); atomicAdd(nb + 3 * i1 + 1, ny); atomicAdd(nb + 3 * i1 + 2, nz);
    atomicAdd(nb + 3 * i2,     nx); atomicAdd(nb + 3 * i2 + 1, ny); atomicAdd(nb + 3 * i2 + 2, nz);
}

// ---------------------------------------------------------------------------
// K3: Laplacian loss. Edge list is sorted by src (np.unique lexicographic),
// and the edge set is symmetric, so nbr_sum[s] = sum over the contiguous
// segment of edges with src==s of v[dst]. Segment-head threads walk their
// segment (degree <= 6) — no atomics, no nbr buffer. Fused with the
// (lap - tl)^2 loss.  grid.y = batch.
// ---------------------------------------------------------------------------
__global__ void k_lap(const int* __restrict__ src, const int* __restrict__ dst,
                      const float* __restrict__ deg,
                      const float* __restrict__ target, int E) {
    int i = blockIdx.x * blockDim.x + threadIdx.x;
    int b = blockIdx.y;
    float local = 0.0f;
    if (i < E) {
        int s = src[i];
        bool head = (i == 0) || (src[i - 1] != s);
        if (head) {
            const float* vb = g_v + (size_t)b * NV3;
            float sx = 0.f, sy = 0.f, sz = 0.f;
            int j = i;
            while (j < E && src[j] == s) {
                int d = dst[j];
                sx += vb[3 * d]; sy += vb[3 * d + 1]; sz += vb[3 * d + 2];
                j++;
            }
            float invd = 1.0f / deg[s];
            float lx = vb[3 * s]     - sx * invd;
            float ly = vb[3 * s + 1] - sy * invd;
            float lz = vb[3 * s + 2] - sz * invd;
            const float* t = target + (size_t)b * 9 * NV;
            float dx = lx - t[6 * (size_t)NV + s];
            float dy = ly - t[7 * (size_t)NV + s];
            float dz = lz - t[8 * (size_t)NV + s];
            local = dx * dx + dy * dy + dz * dz;
        }
    }
    __shared__ float sh[256];
    sh[threadIdx.x] = local;
    __syncthreads();
    for (int st = 128; st > 0; st >>= 1) {
        if (threadIdx.x < st) sh[threadIdx.x] += sh[threadIdx.x + st];
        __syncthreads();
    }
    if (threadIdx.x == 0) atomicAdd(&g_acc[2], (double)sh[0]);
}

// ---------------------------------------------------------------------------
// K4: position loss + normal (cosine) loss.  grid.y = batch.
// ---------------------------------------------------------------------------
__global__ void k_posnor(const float* __restrict__ target) {
    int vtx = blockIdx.x * blockDim.x + threadIdx.x;
    int b   = blockIdx.y;
    float lpos = 0.0f, lnor = 0.0f;
    if (vtx < NV) {
        const float* vb = g_v  + ((size_t)b * NV + vtx) * 3;
        const float* nb = g_vn + ((size_t)b * NV + vtx) * 3;
        const float* t  = target + (size_t)b * 9 * NV + vtx;

        float vx = vb[0], vy = vb[1], vz = vb[2];
        float dx = vx - t[0];
        float dy = vy - t[(size_t)NV];
        float dz = vz - t[2 * (size_t)NV];
        lpos = dx * dx + dy * dy + dz * dz;

        float nx = nb[0], ny = nb[1], nz = nb[2];
        float nn = sqrtf(nx * nx + ny * ny + nz * nz);
        float inv = 1.0f / fmaxf(nn, 1e-12f);
        float ux = nx * inv, uy = ny * inv, uz = nz * inv;
        float un = sqrtf(ux * ux + uy * uy + uz * uz);
        float tx = t[3 * (size_t)NV], ty = t[4 * (size_t)NV], tz = t[5 * (size_t)NV];
        float tn = sqrtf(tx * tx + ty * ty + tz * tz);
        float cosv = (ux * tx + uy * ty + uz * tz) / fmaxf(un * tn, 1e-8f);
        lnor = 1.0f - cosv;
    }
    __shared__ float shp[256];
    __shared__ float shn[256];
    shp[threadIdx.x] = lpos;
    shn[threadIdx.x] = lnor;
    __syncthreads();
    for (int st = 128; st > 0; st >>= 1) {
        if (threadIdx.x < st) {
            shp[threadIdx.x] += shp[threadIdx.x + st];
            shn[threadIdx.x] += shn[threadIdx.x + st];
        }
        __syncthreads();
    }
    if (threadIdx.x == 0) {
        atomicAdd(&g_acc[0], (double)shp[0]);
        atomicAdd(&g_acc[1], (double)shn[0]);
    }
}

// ---------------------------------------------------------------------------
// K5: combine into the scalar output
// ---------------------------------------------------------------------------
__global__ void k_final(float* __restrict__ out) {
    if (threadIdx.x == 0 && blockIdx.x == 0) {
        double n3 = (double)BATCH * NV * 3.0;
        double n1 = (double)BATCH * NV;
        out[0] = (float)(g_acc[0] / n3 + g_acc[1] / n1 + g_acc[2] / n3);
    }
}

extern "C" void kernel_launch(void* const* d_in, const int* in_sizes, int n_in,
                              void* d_out, int out_size) {
    const float* inputs = (const float*)d_in[0];
    const float* target = (const float*)d_in[1];
    const int*   faces  = (const int*)  d_in[2];
    const int*   esrc   = (const int*)  d_in[3];
    const int*   edst   = (const int*)  d_in[4];
    const float* deg    = (const float*)d_in[5];
    int F = in_sizes[2] / 3;
    int E = in_sizes[3];

    dim3 blk(256);
    long long zn = (long long)BATCH * NV3;
    k_zero   <<<(unsigned)((zn + 255) / 256), blk>>>();
    k_build_v<<<dim3((YX + 2 + 255) / 256, BATCH), blk>>>(inputs);
    k_faces  <<<dim3((F + 255) / 256, BATCH), blk>>>(faces, F);
    k_lap    <<<dim3((E + 255) / 256, BATCH), blk>>>(esrc, edst, deg, target, E);
    k_posnor <<<dim3((NV + 255) / 256, BATCH), blk>>>(target);
    k_final  <<<1, 32>>>((float*)d_out);
}

// round 2
// speedup vs baseline: 4.7867x; 4.7867x over previous
#include <cuda_runtime.h>

// Problem constants (SUBDIVISIONS=7, BATCH=16)
#define BATCH 16
#define YDIM  640
#define XDIM  256
#define BH    128            // YDIM/5
#define YX    (YDIM*XDIM)    // 163840
#define NV    (YX + 2)       // 163842 vertices
#define NV3   (NV*3)
#define BPT   4              // batches per thread in the fused loss kernel

// Scratch (static __device__ — no allocation allowed)
__device__ float  g_v[BATCH * NV3];     // interleaved xyz per batch (~31.5 MB)
__device__ int    g_cnt[NV];            // per-vertex ring fill counters
__device__ int2   g_ring[NV * 6];       // per-vertex opposite-edge pairs (a,b)
__device__ double g_acc;                // single fused loss accumulator

// ---------------------------------------------------------------------------
// K0: zero counters + accumulator
// ---------------------------------------------------------------------------
__global__ void k_zero() {
    int i = blockIdx.x * blockDim.x + threadIdx.x;
    if (i < NV) g_cnt[i] = 0;
    if (i == 0) g_acc = 0.0;
}

// ---------------------------------------------------------------------------
// K1: build v = [grid verts ; top pole ; bottom pole], interleaved xyz
// inputs layout: (B, 3, Y, X) row-major
// ---------------------------------------------------------------------------
__global__ void k_build_v(const float* __restrict__ inp) {
    int vtx = blockIdx.x * blockDim.x + threadIdx.x;
    int b   = blockIdx.y;
    if (vtx > YX + 1) return;
    const float* base = inp + (size_t)b * 3 * YX;
    float* out = g_v + ((size_t)b * NV + vtx) * 3;
    if (vtx < YX) {
        out[0] = base[vtx];
        out[1] = base[YX + vtx];
        out[2] = base[2 * YX + vtx];
    } else if (vtx == YX) {
        #pragma unroll
        for (int c = 0; c < 3; c++) {
            float s = 0.0f;
            #pragma unroll
            for (int i = 0; i < 5; i++) s += base[c * YX + (i * BH) * XDIM];
            out[c] = s * 0.2f;
        }
    } else {
        #pragma unroll
        for (int c = 0; c < 3; c++) {
            float s = 0.0f;
            #pragma unroll
            for (int i = 1; i <= 5; i++)
                s += base[c * YX + (i * BH - 1) * XDIM + (XDIM - 1)];
            out[c] = s * 0.2f;
        }
    }
}

// ---------------------------------------------------------------------------
// K2: build the per-vertex ring list of opposite-edge pairs from faces.
// Face (f0,f1,f2) contributes pair (f1,f2) to f0, (f2,f0) to f1, (f0,f1) to f2.
// Identity: cross(v1-v0,v2-v0) = v0xv1 + v1xv2 + v2xv0, and around a closed
// vertex ring the v-dependent terms cancel, so vn[v] = sum of a x b over its
// opposite-edge pairs. Also sum of a_i == one-ring neighbor sum (Laplacian).
// Batch-independent: built once per launch.
// ---------------------------------------------------------------------------
__global__ void k_ring(const int* __restrict__ faces, int F) {
    int f = blockIdx.x * blockDim.x + threadIdx.x;
    if (f >= F) return;
    int a = faces[3 * f], b = faces[3 * f + 1], c = faces[3 * f + 2];
    int s;
    s = atomicAdd(&g_cnt[a], 1); g_ring[a * 6 + s] = make_int2(b, c);
    s = atomicAdd(&g_cnt[b], 1); g_ring[b * 6 + s] = make_int2(c, a);
    s = atomicAdd(&g_cnt[c], 1); g_ring[c * 6 + s] = make_int2(a, b);
}

// ---------------------------------------------------------------------------
// K3: fused loss. One thread per vertex, BPT batches per thread.
// Per vertex: read ring pairs once, build permutation sigma so that
// b_i == a_{sigma[i]} (neighbors are reused — only 6 vec3 gathers per batch).
// Computes pos + normal-cosine + Laplacian losses in one pass.
// ---------------------------------------------------------------------------
__global__ void k_loss(const float* __restrict__ target,
                       const float* __restrict__ degree) {
    int vtx = blockIdx.x * blockDim.x + threadIdx.x;
    float local = 0.0f;
    if (vtx < NV) {
        int cnt = g_cnt[vtx];            // 5 or 6
        int2 pr[6];
        int  ia[6], sig[6];
        #pragma unroll
        for (int i = 0; i < 6; i++)
            pr[i] = (i < cnt) ? g_ring[vtx * 6 + i] : make_int2(0, 0);
        #pragma unroll
        for (int i = 0; i < 6; i++) ia[i] = pr[i].x;
        #pragma unroll
        for (int i = 0; i < 6; i++) {
            int s_ = 0;
            #pragma unroll
            for (int j = 0; j < 6; j++)
                if (j < cnt && ia[j] == pr[i].y) s_ = j;
            sig[i] = s_;
        }
        float invd = 1.0f / degree[vtx];
        const float inv3 = 1.0f / 3.0f;

        #pragma unroll
        for (int bb = 0; bb < BPT; bb++) {
            int b = blockIdx.y * BPT + bb;
            const float* vb = g_v + (size_t)b * NV3;

            float pax[6], pay[6], paz[6];
            #pragma unroll
            for (int i = 0; i < 6; i++) {
                const float* p = vb + 3 * (size_t)ia[i];
                pax[i] = p[0]; pay[i] = p[1]; paz[i] = p[2];
            }

            float sx = 0.f, sy = 0.f, sz = 0.f;
            float nx = 0.f, ny = 0.f, nz = 0.f;
            #pragma unroll
            for (int i = 0; i < 6; i++) {
                if (i < cnt) {
                    sx += pax[i]; sy += pay[i]; sz += paz[i];
                    int j = sig[i];
                    nx += pay[i] * paz[j] - paz[i] * pay[j];
                    ny += paz[i] * pax[j] - pax[i] * paz[j];
                    nz += pax[i] * pay[j] - pay[i] * pax[j];
                }
            }

            const float* pv = vb + 3 * (size_t)vtx;
            float vx = pv[0], vy = pv[1], vz = pv[2];

            const float* t = target + (size_t)b * 9 * NV + vtx;
            // position loss
            float dx = vx - t[0];
            float dy = vy - t[(size_t)NV];
            float dz = vz - t[2 * (size_t)NV];
            float lpos = dx * dx + dy * dy + dz * dz;
            // normal cosine loss
            float nn  = sqrtf(nx * nx + ny * ny + nz * nz);
            float inv = 1.0f / fmaxf(nn, 1e-12f);
            float ux = nx * inv, uy = ny * inv, uz = nz * inv;
            float un = sqrtf(ux * ux + uy * uy + uz * uz);
            float tx = t[3 * (size_t)NV], ty = t[4 * (size_t)NV], tz = t[5 * (size_t)NV];
            float tn = sqrtf(tx * tx + ty * ty + tz * tz);
            float cosv = (ux * tx + uy * ty + uz * tz) / fmaxf(un * tn, 1e-8f);
            // Laplacian loss
            float lx = vx - sx * invd;
            float ly = vy - sy * invd;
            float lz = vz - sz * invd;
            float dlx = lx - t[6 * (size_t)NV];
            float dly = ly - t[7 * (size_t)NV];
            float dlz = lz - t[8 * (size_t)NV];
            float llap = dlx * dlx + dly * dly + dlz * dlz;

            local += (lpos + llap) * inv3 + (1.0f - cosv);
        }
    }

    // block tree-reduce, one double atomic per block
    __shared__ float sh[128];
    sh[threadIdx.x] = local;
    __syncthreads();
    for (int st = 64; st > 0; st >>= 1) {
        if (threadIdx.x < st) sh[threadIdx.x] += sh[threadIdx.x + st];
        __syncthreads();
    }
    if (threadIdx.x == 0) atomicAdd(&g_acc, (double)sh[0]);
}

// ---------------------------------------------------------------------------
// K4: final scalar
// ---------------------------------------------------------------------------
__global__ void k_final(float* __restrict__ out) {
    if (threadIdx.x == 0 && blockIdx.x == 0)
        out[0] = (float)(g_acc / ((double)BATCH * (double)NV));
}

extern "C" void kernel_launch(void* const* d_in, const int* in_sizes, int n_in,
                              void* d_out, int out_size) {
    const float* inputs = (const float*)d_in[0];
    const float* target = (const float*)d_in[1];
    const int*   faces  = (const int*)  d_in[2];
    const float* deg    = (const float*)d_in[5];
    int F = in_sizes[2] / 3;

    dim3 blk256(256);
    k_zero   <<<(NV + 255) / 256, blk256>>>();
    k_build_v<<<dim3((YX + 2 + 255) / 256, BATCH), blk256>>>(inputs);
    k_ring   <<<(F + 255) / 256, blk256>>>(faces, F);
    k_loss   <<<dim3((NV + 127) / 128, BATCH / BPT), 128>>>(target, deg);
    k_final  <<<1, 32>>>((float*)d_out);
}

// round 3
// speedup vs baseline: 5.9121x; 1.2351x over previous
#include <cuda_runtime.h>

// Problem constants (SUBDIVISIONS=7, BATCH=16)
#define BATCH 16
#define YDIM  640
#define XDIM  256
#define BH    128            // YDIM/5
#define YX    (YDIM*XDIM)    // 163840
#define NV    (YX + 2)       // 163842 vertices
#define BPT   4              // batches per thread in the fused loss kernel

// Scratch (static __device__ — no allocation allowed)
__device__ float4 g_v4[BATCH * NV];   // padded xyz_ per batch (~42 MB)
__device__ int    g_cnt[NV];          // per-vertex ring fill counters
__device__ int2   g_ring[NV * 6];     // per-vertex opposite-edge pairs (a,b)
__device__ int4   g_nbr[NV * 2];      // ring-ordered neighbors: [n0..n5, cnt, _]
__device__ double g_acc;              // fused loss accumulator

// ---------------------------------------------------------------------------
// K0: zero counters + accumulator
// ---------------------------------------------------------------------------
__global__ void k_zero() {
    int i = blockIdx.x * blockDim.x + threadIdx.x;
    if (i < NV) g_cnt[i] = 0;
    if (i == 0) g_acc = 0.0;
}

// ---------------------------------------------------------------------------
// K1: build v = [grid verts ; top pole ; bottom pole] as float4 (w unused)
// inputs layout: (B, 3, Y, X) row-major
// ---------------------------------------------------------------------------
__global__ void k_build_v(const float* __restrict__ inp) {
    int vtx = blockIdx.x * blockDim.x + threadIdx.x;
    int b   = blockIdx.y;
    if (vtx > YX + 1) return;
    const float* base = inp + (size_t)b * 3 * YX;
    float4 o;
    o.w = 0.0f;
    if (vtx < YX) {
        o.x = base[vtx];
        o.y = base[YX + vtx];
        o.z = base[2 * YX + vtx];
    } else if (vtx == YX) {
        float s[3];
        #pragma unroll
        for (int c = 0; c < 3; c++) {
            s[c] = 0.0f;
            #pragma unroll
            for (int i = 0; i < 5; i++) s[c] += base[c * YX + (i * BH) * XDIM];
            s[c] *= 0.2f;
        }
        o.x = s[0]; o.y = s[1]; o.z = s[2];
    } else {
        float s[3];
        #pragma unroll
        for (int c = 0; c < 3; c++) {
            s[c] = 0.0f;
            #pragma unroll
            for (int i = 1; i <= 5; i++)
                s[c] += base[c * YX + (i * BH - 1) * XDIM + (XDIM - 1)];
            s[c] *= 0.2f;
        }
        o.x = s[0]; o.y = s[1]; o.z = s[2];
    }
    g_v4[(size_t)b * NV + vtx] = o;
}

// ---------------------------------------------------------------------------
// K2: collect per-vertex opposite-edge pairs from faces (batch-independent).
// Face (f0,f1,f2): pair (f1,f2)->f0, (f2,f0)->f1, (f0,f1)->f2.
// Identity: sum of full face normals around a closed ring telescopes to
// vn[v] = sum_i a_i x b_i over opposite-edge pairs.
// ---------------------------------------------------------------------------
__global__ void k_ring(const int* __restrict__ faces, int F) {
    int f = blockIdx.x * blockDim.x + threadIdx.x;
    if (f >= F) return;
    int a = faces[3 * f], b = faces[3 * f + 1], c = faces[3 * f + 2];
    int s;
    s = atomicAdd(&g_cnt[a], 1); g_ring[a * 6 + s] = make_int2(b, c);
    s = atomicAdd(&g_cnt[b], 1); g_ring[b * 6 + s] = make_int2(c, a);
    s = atomicAdd(&g_cnt[c], 1); g_ring[c * 6 + s] = make_int2(a, b);
}

// ---------------------------------------------------------------------------
// K2b: chain the pairs into a cyclic ring order: n_{j+1} = next(n_j).
// Then vn[v] = sum_j n_j x n_{j+1 mod cnt}. For cnt==5, slot 5 duplicates
// n_0 so the wrap term n5 x n0 = n0 x n0 = 0 and six fixed cross terms work.
// ---------------------------------------------------------------------------
__global__ void k_order(int NVv) {
    int v = blockIdx.x * blockDim.x + threadIdx.x;
    if (v >= NVv) return;
    int cnt = g_cnt[v];
    int2 pr[6];
    #pragma unroll
    for (int i = 0; i < 6; i++)
        pr[i] = (i < cnt) ? g_ring[v * 6 + i] : make_int2(-1, -1);
    int ord[6];
    ord[0] = pr[0].x;
    int cur = pr[0].y;
    #pragma unroll
    for (int k = 1; k < 6; k++) {
        ord[k] = cur;
        int nxt = cur;
        #pragma unroll
        for (int i = 0; i < 6; i++)
            if (pr[i].x == cur) nxt = pr[i].y;
        cur = nxt;
    }
    if (cnt == 5) ord[5] = ord[0];   // duplicate: wrap cross term vanishes
    g_nbr[2 * v]     = make_int4(ord[0], ord[1], ord[2], ord[3]);
    g_nbr[2 * v + 1] = make_int4(ord[4], ord[5], cnt, 0);
}

// ---------------------------------------------------------------------------
// K3: fused loss. One thread per vertex, BPT batches per thread.
// 7 LDG.128 gathers + 2 LDG.128 index reads (amortized) per vertex-batch.
// ---------------------------------------------------------------------------
__global__ void __launch_bounds__(128) k_loss(const float* __restrict__ target,
                                             const float* __restrict__ degree) {
    int vtx = blockIdx.x * blockDim.x + threadIdx.x;
    float local = 0.0f;
    if (vtx < NV) {
        int4 lo = g_nbr[2 * vtx];
        int4 hi = g_nbr[2 * vtx + 1];
        int n[6] = {lo.x, lo.y, lo.z, lo.w, hi.x, hi.y};
        int cnt  = hi.z;
        float invd = 1.0f / degree[vtx];
        const float inv3 = 1.0f / 3.0f;

        #pragma unroll
        for (int bb = 0; bb < BPT; bb++) {
            int b = blockIdx.y * BPT + bb;
            const float4* vb = g_v4 + (size_t)b * NV;

            float4 p[6];
            #pragma unroll
            for (int i = 0; i < 6; i++) p[i] = __ldg(vb + n[i]);
            float4 pv = __ldg(vb + vtx);

            // ring-ordered cross sum: vn = sum_j p_j x p_{(j+1)%6}
            float nx = 0.f, ny = 0.f, nz = 0.f;
            #pragma unroll
            for (int j = 0; j < 6; j++) {
                const float4 a = p[j];
                const float4 c = p[(j + 1) % 6];
                nx += a.y * c.z - a.z * c.y;
                ny += a.z * c.x - a.x * c.z;
                nz += a.x * c.y - a.y * c.x;
            }
            // neighbor sum (subtract the duplicated n0 if deg==5)
            float sx = 0.f, sy = 0.f, sz = 0.f;
            #pragma unroll
            for (int j = 0; j < 6; j++) { sx += p[j].x; sy += p[j].y; sz += p[j].z; }
            if (cnt == 5) { sx -= p[0].x; sy -= p[0].y; sz -= p[0].z; }

            const float* t = target + (size_t)b * 9 * NV + vtx;
            // position loss
            float dx = pv.x - t[0];
            float dy = pv.y - t[(size_t)NV];
            float dz = pv.z - t[2 * (size_t)NV];
            float lpos = dx * dx + dy * dy + dz * dz;
            // normal cosine loss
            float nn  = sqrtf(nx * nx + ny * ny + nz * nz);
            float inv = 1.0f / fmaxf(nn, 1e-12f);
            float ux = nx * inv, uy = ny * inv, uz = nz * inv;
            float un = sqrtf(ux * ux + uy * uy + uz * uz);
            float tx = t[3 * (size_t)NV], ty = t[4 * (size_t)NV], tz = t[5 * (size_t)NV];
            float tn = sqrtf(tx * tx + ty * ty + tz * tz);
            float cosv = (ux * tx + uy * ty + uz * tz) / fmaxf(un * tn, 1e-8f);
            // Laplacian loss
            float dlx = (pv.x - sx * invd) - t[6 * (size_t)NV];
            float dly = (pv.y - sy * invd) - t[7 * (size_t)NV];
            float dlz = (pv.z - sz * invd) - t[8 * (size_t)NV];
            float llap = dlx * dlx + dly * dly + dlz * dlz;

            local += (lpos + llap) * inv3 + (1.0f - cosv);
        }
    }

    // block tree-reduce, one double atomic per block
    __shared__ float sh[128];
    sh[threadIdx.x] = local;
    __syncthreads();
    for (int st = 64; st > 0; st >>= 1) {
        if (threadIdx.x < st) sh[threadIdx.x] += sh[threadIdx.x + st];
        __syncthreads();
    }
    if (threadIdx.x == 0) atomicAdd(&g_acc, (double)sh[0]);
}

// ---------------------------------------------------------------------------
// K4: final scalar
// ---------------------------------------------------------------------------
__global__ void k_final(float* __restrict__ out) {
    if (threadIdx.x == 0 && blockIdx.x == 0)
        out[0] = (float)(g_acc / ((double)BATCH * (double)NV));
}

extern "C" void kernel_launch(void* const* d_in, const int* in_sizes, int n_in,
                              void* d_out, int out_size) {
    const float* inputs = (const float*)d_in[0];
    const float* target = (const float*)d_in[1];
    const int*   faces  = (const int*)  d_in[2];
    const float* deg    = (const float*)d_in[5];
    int F = in_sizes[2] / 3;

    dim3 blk256(256);
    k_zero   <<<(NV + 255) / 256, blk256>>>();
    k_build_v<<<dim3((YX + 2 + 255) / 256, BATCH), blk256>>>(inputs);
    k_ring   <<<(F + 255) / 256, blk256>>>(faces, F);
    k_order  <<<(NV + 255) / 256, blk256>>>(NV);
    k_loss   <<<dim3((NV + 127) / 128, BATCH / BPT), 128>>>(target, deg);
    k_final  <<<1, 32>>>((float*)d_out);
}